// round 16
// baseline (speedup 1.0000x reference)
#include <cuda_runtime.h>
#include <cuda_bf16.h>
#include <math.h>
#include <stdint.h>

// ---------------------------------------------------------------------------
// Scratch (device globals; no allocation allowed)
// q/k stored as fp8 e4m3 in ldsm-swizzled layout: row stride 256B,
// byte_off(row, col) = row*256 + (((col>>4) ^ (row&7))<<4) + (col&15)
// q arrays are PRE-SCALED by 0.125 (exact in e4m3).
// ---------------------------------------------------------------------------
__device__ __align__(16) char g_q_lang[2048 * 256];
__device__ __align__(16) char g_k_lang[2048 * 256];
__device__ __align__(16) char g_q_vis [8192 * 256];
__device__ __align__(16) char g_k_vis [8192 * 256];
__device__ float g_part[2 * 32 * 32 * 8];   // [dir][i][j][slot], zero-init

// ---------------------------------------------------------------------------
// helpers
// ---------------------------------------------------------------------------
__device__ __forceinline__ uint16_t pack_fp8x2(float lo, float hi) {
    uint16_t r;
    asm("cvt.rn.satfinite.e4m3x2.f32 %0, %1, %2;" : "=h"(r) : "f"(hi), "f"(lo));
    return r;
}
__device__ __forceinline__ uint32_t f2tf32(float v) {
    uint32_t r;
    asm("cvt.rna.tf32.f32 %0, %1;" : "=r"(r) : "f"(v));
    return r;
}
__device__ __forceinline__ void mma_tf32(float c[4],
                                         uint32_t a0, uint32_t a1, uint32_t a2, uint32_t a3,
                                         uint32_t b0, uint32_t b1)
{
    asm volatile(
        "mma.sync.aligned.m16n8k8.row.col.f32.tf32.tf32.f32 "
        "{%0,%1,%2,%3}, {%4,%5,%6,%7}, {%8,%9}, {%0,%1,%2,%3};\n"
        : "+f"(c[0]), "+f"(c[1]), "+f"(c[2]), "+f"(c[3])
        : "r"(a0), "r"(a1), "r"(a2), "r"(a3), "r"(b0), "r"(b1));
}
__device__ __forceinline__ void cpasync16(uint32_t s, const void* g) {
    asm volatile("cp.async.cg.shared.global [%0], [%1], 16;\n" :: "r"(s), "l"(g));
}
__device__ __forceinline__ void cpasync_commit() {
    asm volatile("cp.async.commit_group;\n");
}
__device__ __forceinline__ void cpasync_wait_all() {
    asm volatile("cp.async.wait_group 0;\n");
}
__device__ __forceinline__ void ldsm_x4(uint32_t& r0, uint32_t& r1,
                                        uint32_t& r2, uint32_t& r3, uint32_t addr) {
    asm volatile("ldmatrix.sync.aligned.m8n8.x4.shared.b16 {%0,%1,%2,%3}, [%4];"
                 : "=r"(r0), "=r"(r1), "=r"(r2), "=r"(r3) : "r"(addr));
}
__device__ __forceinline__ void mma_fp8(float c[4],
                                        uint32_t a0, uint32_t a1, uint32_t a2, uint32_t a3,
                                        uint32_t b0, uint32_t b1) {
    asm volatile(
        "mma.sync.aligned.m16n8k32.row.col.f32.e4m3.e4m3.f32 "
        "{%0,%1,%2,%3}, {%4,%5,%6,%7}, {%8,%9}, {%0,%1,%2,%3};\n"
        : "+f"(c[0]), "+f"(c[1]), "+f"(c[2]), "+f"(c[3])
        : "r"(a0), "r"(a1), "r"(a2), "r"(a3), "r"(b0), "r"(b1));
}

// ---------------------------------------------------------------------------
// Kernel A: projection GEMM (tf32) -> fp8 swizzled q/k arrays.
// q outputs are scaled by 0.125 (exact power of 2 in e4m3).
// ---------------------------------------------------------------------------
__global__ void __launch_bounds__(256) proj_tc(const float* __restrict__ X,
                                               const float* __restrict__ W,
                                               const float* __restrict__ bias,
                                               int which, int bx0)
{
    extern __shared__ uint32_t smemU[];
    uint32_t* As = smemU;               // [128][68]
    uint32_t* Bs = smemU + 128 * 68;    // [64][68]

    const int n0  = (blockIdx.x + bx0) * 64;
    const int m0  = blockIdx.y * 128;
    const int tid = threadIdx.x;
    const int w    = tid >> 5;
    const int lane = tid & 31;

    const int wm = (w & 3) * 32;
    const int wn = (w >> 2) * 32;
    const int qrow = lane >> 2;
    const int qcol = lane & 3;

    float c[2][4][4] = {};

    for (int k0 = 0; k0 < 256; k0 += 64) {
        __syncthreads();
        #pragma unroll
        for (int it = 0; it < 8; ++it) {
            int id = tid + it * 256;
            int r  = id >> 4;
            int q  = id & 15;
            float4 v = *(const float4*)(X + (size_t)(m0 + r) * 256 + k0 + q * 4);
            uint32_t* d = As + r * 68 + q * 4;
            d[0] = f2tf32(v.x); d[1] = f2tf32(v.y); d[2] = f2tf32(v.z); d[3] = f2tf32(v.w);
        }
        #pragma unroll
        for (int it = 0; it < 4; ++it) {
            int id = tid + it * 256;
            int r  = id >> 4;
            int q  = id & 15;
            float4 v = *(const float4*)(W + (size_t)(n0 + r) * 256 + k0 + q * 4);
            uint32_t* d = Bs + r * 68 + q * 4;
            d[0] = f2tf32(v.x); d[1] = f2tf32(v.y); d[2] = f2tf32(v.z); d[3] = f2tf32(v.w);
        }
        __syncthreads();

        const uint32_t* Aw = As + wm * 68;
        const uint32_t* Bw = Bs + wn * 68;
        #pragma unroll
        for (int kk = 0; kk < 8; ++kk) {
            uint32_t a[2][4];
            #pragma unroll
            for (int mt = 0; mt < 2; ++mt) {
                const uint32_t* p = Aw + (mt * 16 + qrow) * 68 + kk * 8 + qcol;
                a[mt][0] = p[0];
                a[mt][1] = p[8 * 68];
                a[mt][2] = p[4];
                a[mt][3] = p[8 * 68 + 4];
            }
            uint32_t b[4][2];
            #pragma unroll
            for (int nt = 0; nt < 4; ++nt) {
                const uint32_t* p = Bw + (nt * 8 + qrow) * 68 + kk * 8 + qcol;
                b[nt][0] = p[0];
                b[nt][1] = p[4];
            }
            #pragma unroll
            for (int mt = 0; mt < 2; ++mt)
                #pragma unroll
                for (int nt = 0; nt < 4; ++nt)
                    mma_tf32(c[mt][nt], a[mt][0], a[mt][1], a[mt][2], a[mt][3],
                             b[nt][0], b[nt][1]);
        }
    }

    const bool isq = (n0 < 256);
    char* arr = which ? (isq ? g_q_vis : g_k_vis) : (isq ? g_q_lang : g_k_lang);
    const float qsc = isq ? 0.125f : 1.0f;   // fold 1/sqrt(hd) into q (exact)

    #pragma unroll
    for (int mt = 0; mt < 2; ++mt) {
        #pragma unroll
        for (int nt = 0; nt < 4; ++nt) {
            const int n  = n0 + wn + nt * 8 + qcol * 2;
            const int cl = n & 255;
            const float b0 = __ldg(bias + n), b1 = __ldg(bias + n + 1);
            const int r0 = m0 + wm + mt * 16 + qrow;
            const int r1 = r0 + 8;
            uint16_t v0 = pack_fp8x2((c[mt][nt][0] + b0) * qsc, (c[mt][nt][1] + b1) * qsc);
            uint16_t v1 = pack_fp8x2((c[mt][nt][2] + b0) * qsc, (c[mt][nt][3] + b1) * qsc);
            uint32_t o0 = (uint32_t)r0 * 256 + ((((cl >> 4) ^ (r0 & 7)) << 4) | (cl & 15));
            uint32_t o1 = (uint32_t)r1 * 256 + ((((cl >> 4) ^ (r1 & 7)) << 4) | (cl & 15));
            *(uint16_t*)(arr + o0) = v0;
            *(uint16_t*)(arr + o1) = v1;
        }
    }
}

// ---------------------------------------------------------------------------
// top3 helper — branchless sorted-triple local insert + shuffle merge.
// ---------------------------------------------------------------------------
template<int NB>
__device__ __forceinline__ float top3_sum(const float* v, int lane) {
    float t1 = -1e30f, t2 = -1e30f, t3 = -1e30f;
    #pragma unroll
    for (int bi = 0; bi < NB; ++bi) {
        float x  = v[bi * 32 + lane];
        float m2 = fminf(t1, x);
        t1 = fmaxf(t1, x);
        t3 = fmaxf(t3, fminf(t2, m2));
        t2 = fmaxf(t2, m2);
    }
    #pragma unroll
    for (int off = 16; off; off >>= 1) {
        float o1 = __shfl_xor_sync(0xffffffffu, t1, off);
        float o2 = __shfl_xor_sync(0xffffffffu, t2, off);
        float o3 = __shfl_xor_sync(0xffffffffu, t3, off);
        float c1 = fmaxf(t1, o1);
        float c2 = fmaxf(fminf(t1, o1), fmaxf(t2, o2));
        float c3 = fmaxf(fmaxf(fminf(t1, o2), fminf(t2, o1)), fmaxf(t3, o3));
        t1 = c1; t2 = c2; t3 = c3;
    }
    return t1 + t2 + t3;
}

// ---------------------------------------------------------------------------
// Kernel B1: v2t fused sim (fp8, pre-scaled q). WR=2, WC=4: M=32, NT=64.
// 256 thr, 3 CTAs/SM. grid (32,8) x NITER=32 -> 256 blocks = single wave.
// ---------------------------------------------------------------------------
__global__ void __launch_bounds__(256, 3)
sim_v2t(const char* __restrict__ anch_q,
        const char* __restrict__ targ_k,
        float* __restrict__ part)
{
    constexpr int WC = 4, M = 32, NT = 64, NITER = 32;
    constexpr int AMS = NT + 4;
    constexpr int OFF_B    = 0;
    constexpr int OFF_A    = OFF_B + NT * 256;
    constexpr int OFF_AM   = OFF_A + M * 256;
    constexpr int OFF_RED  = OFF_AM + M * AMS * 4;
    constexpr int OFF_WACC = OFF_RED + 4 * WC * M * 4;

    extern __shared__ char smem[];
    const uint32_t sbase = (uint32_t)__cvta_generic_to_shared(smem);

    const int j    = blockIdx.x;
    const int z    = blockIdx.y;
    const int tid  = threadIdx.x;
    const int w    = tid >> 5;
    const int lane = tid & 31;

    {
        const char* src = targ_k + (size_t)j * NT * 256;
        #pragma unroll
        for (int id = tid; id < NT * 16; id += 256)
            cpasync16(sbase + OFF_B + id * 16, src + id * 16);
        cpasync_commit();
    }

    const int wm = (w >> 2) * 16;
    const int wn = (w & 3) * 16;
    const int wc = w & 3;
    const int l8  = lane & 7;
    const int sub = lane >> 3;
    const int qrow = lane >> 2;
    const int qcol = lane & 3;

    const uint32_t a_base = sbase + OFF_A + (uint32_t)(wm + l8 + (sub & 1) * 8) * 256;
    const int      a_coff = sub >> 1;
    const uint32_t b_base = sbase + OFF_B + (uint32_t)(wn + l8 + ((sub >> 1) & 1) * 8) * 256;
    const int      b_coff = sub & 1;

    float* redf  = (float*)(smem + OFF_RED);
    float* amf   = (float*)(smem + OFF_AM);
    float* waccf = (float*)(smem + OFF_WACC);

    for (int it = 0; it < NITER; ++it) {
        const int cidx = z * NITER + it;

        __syncthreads();
        {
            const char* src = anch_q + (size_t)cidx * M * 256;
            #pragma unroll
            for (int id = tid; id < M * 16; id += 256)
                cpasync16(sbase + OFF_A + id * 16, src + id * 16);
            cpasync_commit();
            cpasync_wait_all();
        }
        __syncthreads();

        float am[2][4];
        #pragma unroll
        for (int nt = 0; nt < 2; ++nt)
            #pragma unroll
            for (int e = 0; e < 4; ++e) am[nt][e] = 0.f;

        #pragma unroll
        for (int hp = 0; hp < 4; hp += 2) {
            float c[2][2][4];
            #pragma unroll
            for (int hh = 0; hh < 2; ++hh)
                #pragma unroll
                for (int nt = 0; nt < 2; ++nt)
                    #pragma unroll
                    for (int e = 0; e < 4; ++e) c[hh][nt][e] = 0.f;

            #pragma unroll
            for (int hh = 0; hh < 2; ++hh) {
                const int h = hp + hh;
                #pragma unroll
                for (int s = 0; s < 2; ++s) {
                    const int cq = h * 4 + s * 2;
                    uint32_t a0, a1, a2, a3, p0, p1, p2, p3;
                    ldsm_x4(a0, a1, a2, a3, a_base + (((cq + a_coff) ^ l8) << 4));
                    ldsm_x4(p0, p1, p2, p3, b_base + (((cq + b_coff) ^ l8) << 4));
                    mma_fp8(c[hh][0], a0, a1, a2, a3, p0, p1);
                    mma_fp8(c[hh][1], a0, a1, a2, a3, p2, p3);
                }
            }

            #pragma unroll
            for (int hh = 0; hh < 2; ++hh) {
                const int h = hp + hh;
                float z0 = 0.f, z1 = 0.f;
                #pragma unroll
                for (int nt = 0; nt < 2; ++nt) {
                    c[hh][nt][0] = __expf(c[hh][nt][0]);
                    c[hh][nt][1] = __expf(c[hh][nt][1]);
                    c[hh][nt][2] = __expf(c[hh][nt][2]);
                    c[hh][nt][3] = __expf(c[hh][nt][3]);
                    z0 += c[hh][nt][0] + c[hh][nt][1];
                    z1 += c[hh][nt][2] + c[hh][nt][3];
                }
                z0 += __shfl_xor_sync(0xffffffffu, z0, 1);
                z0 += __shfl_xor_sync(0xffffffffu, z0, 2);
                z1 += __shfl_xor_sync(0xffffffffu, z1, 1);
                z1 += __shfl_xor_sync(0xffffffffu, z1, 2);
                if (qcol == 0) {
                    redf[h * WC * M + wc * M + wm + qrow]     = z0;
                    redf[h * WC * M + wc * M + wm + qrow + 8] = z1;
                }
            }
            __syncthreads();

            float rr[2][2];
            #pragma unroll
            for (int hh = 0; hh < 2; ++hh) {
                const int h = hp + hh;
                #pragma unroll
                for (int rp = 0; rp < 2; ++rp) {
                    float zz = 0.f;
                    #pragma unroll
                    for (int x = 0; x < WC; ++x)
                        zz += redf[h * WC * M + x * M + wm + qrow + rp * 8];
                    rr[hh][rp] = 0.25f / zz;
                }
            }

            #pragma unroll
            for (int nt = 0; nt < 2; ++nt) {
                am[nt][0] += c[0][nt][0] * rr[0][0] + c[1][nt][0] * rr[1][0];
                am[nt][1] += c[0][nt][1] * rr[0][0] + c[1][nt][1] * rr[1][0];
                am[nt][2] += c[0][nt][2] * rr[0][1] + c[1][nt][2] * rr[1][1];
                am[nt][3] += c[0][nt][3] * rr[0][1] + c[1][nt][3] * rr[1][1];
            }
        }

        #pragma unroll
        for (int nt = 0; nt < 2; ++nt) {
            const int colb = wn + nt * 8 + qcol * 2;
            *(float2*)&amf[(wm + qrow)     * AMS + colb] = make_float2(am[nt][0], am[nt][1]);
            *(float2*)&amf[(wm + qrow + 8) * AMS + colb] = make_float2(am[nt][2], am[nt][3]);
        }
        __syncthreads();

        float acc = 0.f;
        #pragma unroll
        for (int r2 = 0; r2 < 4; ++r2)
            acc += top3_sum<2>(&amf[(w * 4 + r2) * AMS], lane);
        if (lane == 0) waccf[w] = acc;
        __syncthreads();
        if (tid == 0) {
            float tot = 0.f;
            #pragma unroll
            for (int x = 0; x < 8; ++x) tot += waccf[x];
            const int i = cidx >> 3, slot = cidx & 7;   // 8 chunks per batch
            part[((i * 32 + j) << 3) + slot] = tot;
        }
    }
}

// ---------------------------------------------------------------------------
// Kernel B2: t2v fused sim (fp8, pre-scaled q). 256 thr, M=16, NT=256.
// HPB=4 single pass; 4 barriers/iter; next A-tile prefetched under top-3.
// grid (32,8) x NITER=16 -> 256 blocks = single wave at 2 CTAs/SM.
// Chunks per batch = 4 -> slot decode >>2 / &3.
// ---------------------------------------------------------------------------
__global__ void __launch_bounds__(256, 2)
sim_t2v(const char* __restrict__ anch_q,
        const char* __restrict__ targ_k,
        float* __restrict__ part)
{
    constexpr int NT = 256, M = 16, NITER = 16, AMS = NT + 4;
    constexpr int OFF_B    = 0;
    constexpr int OFF_A    = OFF_B + NT * 256;
    constexpr int OFF_AM   = OFF_A + M * 256;
    constexpr int OFF_RED  = OFF_AM + M * AMS * 4;
    constexpr int OFF_WACC = OFF_RED + 4 * 8 * M * 4;

    extern __shared__ char smem[];
    const uint32_t sbase = (uint32_t)__cvta_generic_to_shared(smem);

    const int j    = blockIdx.x;
    const int z    = blockIdx.y;
    const int tid  = threadIdx.x;
    const int w    = tid >> 5;
    const int lane = tid & 31;

    // ---- B tile + first A tile ----
    {
        const char* src = targ_k + (size_t)j * NT * 256;
        #pragma unroll
        for (int id = tid; id < NT * 16; id += 256)
            cpasync16(sbase + OFF_B + id * 16, src + id * 16);
        const char* srcA = anch_q + (size_t)(z * NITER) * M * 256;
        if (tid < M * 16)
            cpasync16(sbase + OFF_A + tid * 16, srcA + tid * 16);
        cpasync_commit();
        cpasync_wait_all();
    }
    __syncthreads();

    const int wn = w * 32;
    const int l8  = lane & 7;
    const int sub = lane >> 3;
    const int qrow = lane >> 2;
    const int qcol = lane & 3;

    const uint32_t a_base = sbase + OFF_A + (uint32_t)(l8 + (sub & 1) * 8) * 256;
    const int      a_coff = sub >> 1;
    const uint32_t b_base = sbase + OFF_B + (uint32_t)(wn + l8 + ((sub >> 1) & 1) * 8) * 256;
    const int      b_coff = sub & 1;

    float* redf  = (float*)(smem + OFF_RED);
    float* amf   = (float*)(smem + OFF_AM);
    float* waccf = (float*)(smem + OFF_WACC);

    for (int it = 0; it < NITER; ++it) {
        const int cidx = z * NITER + it;

        // ---- MMA all 4 heads ----
        float c[4][4][4];
        #pragma unroll
        for (int h = 0; h < 4; ++h)
            #pragma unroll
            for (int nt = 0; nt < 4; ++nt)
                #pragma unroll
                for (int e = 0; e < 4; ++e) c[h][nt][e] = 0.f;

        #pragma unroll
        for (int h = 0; h < 4; ++h) {
            #pragma unroll
            for (int s = 0; s < 2; ++s) {
                const int cq = h * 4 + s * 2;
                uint32_t a0, a1, a2, a3, p0, p1, p2, p3, q0, q1, q2, q3;
                ldsm_x4(a0, a1, a2, a3, a_base + (((cq + a_coff) ^ l8) << 4));
                ldsm_x4(p0, p1, p2, p3, b_base + (((cq + b_coff) ^ l8) << 4));
                ldsm_x4(q0, q1, q2, q3, b_base + 16 * 256 + (((cq + b_coff) ^ l8) << 4));
                mma_fp8(c[h][0], a0, a1, a2, a3, p0, p1);
                mma_fp8(c[h][1], a0, a1, a2, a3, p2, p3);
                mma_fp8(c[h][2], a0, a1, a2, a3, q0, q1);
                mma_fp8(c[h][3], a0, a1, a2, a3, q2, q3);
            }
        }

        // ---- exp (scale pre-folded into q) + warp-partial Z, all heads ----
        #pragma unroll
        for (int h = 0; h < 4; ++h) {
            float z0 = 0.f, z1 = 0.f;
            #pragma unroll
            for (int nt = 0; nt < 4; ++nt) {
                c[h][nt][0] = __expf(c[h][nt][0]);
                c[h][nt][1] = __expf(c[h][nt][1]);
                c[h][nt][2] = __expf(c[h][nt][2]);
                c[h][nt][3] = __expf(c[h][nt][3]);
                z0 += c[h][nt][0] + c[h][nt][1];
                z1 += c[h][nt][2] + c[h][nt][3];
            }
            z0 += __shfl_xor_sync(0xffffffffu, z0, 1);
            z0 += __shfl_xor_sync(0xffffffffu, z0, 2);
            z1 += __shfl_xor_sync(0xffffffffu, z1, 1);
            z1 += __shfl_xor_sync(0xffffffffu, z1, 2);
            if (qcol == 0) {
                redf[h * 8 * M + w * M + qrow]     = z0;
                redf[h * 8 * M + w * M + qrow + 8] = z1;
            }
        }
        __syncthreads();   // Z ready; A tile now dead -> prefetch next

        if (it + 1 < NITER) {
            const char* src = anch_q + (size_t)(cidx + 1) * M * 256;
            if (tid < M * 16)
                cpasync16(sbase + OFF_A + tid * 16, src + tid * 16);
            cpasync_commit();
        }

        float rr[4][2];
        #pragma unroll
        for (int h = 0; h < 4; ++h)
            #pragma unroll
            for (int rp = 0; rp < 2; ++rp) {
                float zz = 0.f;
                #pragma unroll
                for (int x = 0; x < 8; ++x)
                    zz += redf[h * 8 * M + x * M + qrow + rp * 8];
                rr[h][rp] = 0.25f / zz;
            }

        // ---- am = head-mean, streamed straight into smem stash ----
        #pragma unroll
        for (int nt = 0; nt < 4; ++nt) {
            float a0 = c[0][nt][0]*rr[0][0] + c[1][nt][0]*rr[1][0]
                     + c[2][nt][0]*rr[2][0] + c[3][nt][0]*rr[3][0];
            float a1 = c[0][nt][1]*rr[0][0] + c[1][nt][1]*rr[1][0]
                     + c[2][nt][1]*rr[2][0] + c[3][nt][1]*rr[3][0];
            float a2 = c[0][nt][2]*rr[0][1] + c[1][nt][2]*rr[1][1]
                     + c[2][nt][2]*rr[2][1] + c[3][nt][2]*rr[3][1];
            float a3 = c[0][nt][3]*rr[0][1] + c[1][nt][3]*rr[1][1]
                     + c[2][nt][3]*rr[2][1] + c[3][nt][3]*rr[3][1];
            const int colb = wn + nt * 8 + qcol * 2;
            *(float2*)&amf[qrow       * AMS + colb] = make_float2(a0, a1);
            *(float2*)&amf[(qrow + 8) * AMS + colb] = make_float2(a2, a3);
        }
        __syncthreads();

        // ---- top-3 per anchor row ----
        float acc = 0.f;
        acc += top3_sum<8>(&amf[(w * 2 + 0) * AMS], lane);
        acc += top3_sum<8>(&amf[(w * 2 + 1) * AMS], lane);
        if (lane == 0) waccf[w] = acc;
        __syncthreads();
        if (tid == 0) {
            float tot = 0.f;
            #pragma unroll
            for (int x = 0; x < 8; ++x) tot += waccf[x];
            const int i = cidx >> 2, slot = cidx & 3;   // 4 chunks per batch
            part[((i * 32 + j) << 3) + slot] = tot;
        }
        cpasync_wait_all();
        __syncthreads();   // A(it+1) ready; amf/waccf consumed
    }
}

// ---------------------------------------------------------------------------
// Kernel C: contrastive loss (8 slots per pair; unused slots stay zero)
// ---------------------------------------------------------------------------
__global__ void loss_kernel(const float* __restrict__ part, float* __restrict__ out)
{
    __shared__ float red[64];
    const int t   = threadIdx.x;
    const int dir = t >> 5;
    const int row = t & 31;
    const float* P = part + dir * 8192;
    const float scale = dir ? (100.f / (3.f * 64.f)) : (100.f / (3.f * 256.f));

    float pos = 0.f;
    float t1 = -1e30f, t2 = -1e30f, t3 = -1e30f;
    for (int j = 0; j < 32; ++j) {
        const float* q = &P[(row * 32 + j) << 3];
        float4 a = *(const float4*)q;
        float4 b = *(const float4*)(q + 4);
        float v = (a.x + a.y + a.z + a.w + b.x + b.y + b.z + b.w) * scale;
        if (j == row) { pos = v; continue; }
        if      (v > t1) { t3 = t2; t2 = t1; t1 = v; }
        else if (v > t2) { t3 = t2; t2 = v; }
        else if (v > t3) { t3 = v; }
    }
    const float invT = 1.0f / 0.07f;
    float l0 = pos * invT, l1 = t1 * invT, l2 = t2 * invT, l3 = t3 * invT;
    float m  = fmaxf(fmaxf(l0, l1), fmaxf(l2, l3));
    float Z  = expf(l0 - m) + expf(l1 - m) + expf(l2 - m) + expf(l3 - m);
    red[t] = -(l0 - m - logf(Z));
    __syncthreads();
    if (t == 0) {
        float s0 = 0.f, s1 = 0.f;
        for (int r = 0; r < 32; ++r) { s0 += red[r]; s1 += red[32 + r]; }
        out[0] = 0.5f * (s0 / 32.f) + 0.5f * (s1 / 32.f);
    }
}

// ---------------------------------------------------------------------------
// Launch: critical-path shaping (t2v needs {q_lang, k_vis} -> start early)
// ---------------------------------------------------------------------------
extern "C" void kernel_launch(void* const* d_in, const int* in_sizes, int n_in,
                              void* d_out, int out_size)
{
    const float* lang = (const float*)d_in[0];
    const float* vis  = (const float*)d_in[1];
    const float* W    = (const float*)d_in[2];
    const float* bias = (const float*)d_in[3];

    const int SM_PROJ = (128 * 68 + 64 * 68) * 4;   // 52,224
    const int SM_V2T  = 64*256 + 32*256 + 32*68*4 + 4*4*32*4 + 32;    // 35,360
    const int SM_T2V  = 256*256 + 16*256 + 16*260*4 + 4*8*16*4 + 32;  // 88,352

    static char *p_ql = nullptr, *p_kl = nullptr, *p_qv = nullptr, *p_kv = nullptr;
    static float *p_part = nullptr;
    static cudaStream_t s2;
    static cudaEvent_t evF, evLang, evT;
    if (!p_ql) {
        cudaGetSymbolAddress((void**)&p_ql, g_q_lang);
        cudaGetSymbolAddress((void**)&p_kl, g_k_lang);
        cudaGetSymbolAddress((void**)&p_qv, g_q_vis);
        cudaGetSymbolAddress((void**)&p_kv, g_k_vis);
        cudaGetSymbolAddress((void**)&p_part, g_part);
        cudaFuncSetAttribute((const void*)proj_tc,
                             cudaFuncAttributeMaxDynamicSharedMemorySize, SM_PROJ);
        cudaFuncSetAttribute((const void*)sim_v2t,
                             cudaFuncAttributeMaxDynamicSharedMemorySize, SM_V2T);
        cudaFuncSetAttribute((const void*)sim_t2v,
                             cudaFuncAttributeMaxDynamicSharedMemorySize, SM_T2V);
        cudaStreamCreateWithFlags(&s2, cudaStreamNonBlocking);
        cudaEventCreateWithFlags(&evF,    cudaEventDisableTiming);
        cudaEventCreateWithFlags(&evLang, cudaEventDisableTiming);
        cudaEventCreateWithFlags(&evT,    cudaEventDisableTiming);
    }

    // fork s2 into the captured graph
    cudaEventRecord(evF, 0);
    cudaStreamWaitEvent(s2, evF, 0);

    // s2: k-half of vis projection, then t2v (the long pole) ASAP
    proj_tc<<<dim3(4, 64), 256, SM_PROJ, s2>>>(vis, W, bias, 1, 4);   // k_vis

    // s0: lang projection (q_lang + k_lang), then q-half of vis
    proj_tc<<<dim3(8, 16), 256, SM_PROJ, 0>>>(lang, W, bias, 0, 0);   // q/k_lang
    cudaEventRecord(evLang, 0);
    proj_tc<<<dim3(4, 64), 256, SM_PROJ, 0>>>(vis, W, bias, 1, 0);    // q_vis

    // t2v: waits k_vis (s2 order) + q_lang (evLang)
    cudaStreamWaitEvent(s2, evLang, 0);
    sim_t2v<<<dim3(32, 8), 256, SM_T2V, s2>>>(p_ql, p_kv, p_part + 8192);

    // v2t: deps (k_lang, q_vis) are both earlier in s0
    sim_v2t<<<dim3(32, 8), 256, SM_V2T, 0>>>(p_qv, p_kl, p_part);

    // join before loss
    cudaEventRecord(evT, s2);
    cudaStreamWaitEvent(0, evT, 0);

    loss_kernel<<<1, 64, 0, 0>>>(p_part, (float*)d_out);
}

// round 17
// speedup vs baseline: 1.2292x; 1.2292x over previous
#include <cuda_runtime.h>
#include <cuda_bf16.h>
#include <math.h>
#include <stdint.h>

// ---------------------------------------------------------------------------
// Scratch (device globals; no allocation allowed)
// q/k stored as fp8 e4m3 in ldsm-swizzled layout: row stride 256B,
// byte_off(row, col) = row*256 + (((col>>4) ^ (row&7))<<4) + (col&15)
// q arrays are PRE-SCALED by 0.125 (exact in e4m3).
// ---------------------------------------------------------------------------
__device__ __align__(16) char g_q_lang[2048 * 256];
__device__ __align__(16) char g_k_lang[2048 * 256];
__device__ __align__(16) char g_q_vis [8192 * 256];
__device__ __align__(16) char g_k_vis [8192 * 256];
__device__ float g_part[2 * 32 * 32 * 8];   // [dir][i][j][slot], zero-init

// ---------------------------------------------------------------------------
// helpers
// ---------------------------------------------------------------------------
__device__ __forceinline__ uint16_t pack_fp8x2(float lo, float hi) {
    uint16_t r;
    asm("cvt.rn.satfinite.e4m3x2.f32 %0, %1, %2;" : "=h"(r) : "f"(hi), "f"(lo));
    return r;
}
__device__ __forceinline__ uint32_t f2tf32(float v) {
    uint32_t r;
    asm("cvt.rna.tf32.f32 %0, %1;" : "=r"(r) : "f"(v));
    return r;
}
__device__ __forceinline__ void mma_tf32(float c[4],
                                         uint32_t a0, uint32_t a1, uint32_t a2, uint32_t a3,
                                         uint32_t b0, uint32_t b1)
{
    asm volatile(
        "mma.sync.aligned.m16n8k8.row.col.f32.tf32.tf32.f32 "
        "{%0,%1,%2,%3}, {%4,%5,%6,%7}, {%8,%9}, {%0,%1,%2,%3};\n"
        : "+f"(c[0]), "+f"(c[1]), "+f"(c[2]), "+f"(c[3])
        : "r"(a0), "r"(a1), "r"(a2), "r"(a3), "r"(b0), "r"(b1));
}
__device__ __forceinline__ void cpasync16(uint32_t s, const void* g) {
    asm volatile("cp.async.cg.shared.global [%0], [%1], 16;\n" :: "r"(s), "l"(g));
}
__device__ __forceinline__ void cpasync_commit() {
    asm volatile("cp.async.commit_group;\n");
}
__device__ __forceinline__ void cpasync_wait_all() {
    asm volatile("cp.async.wait_group 0;\n");
}
__device__ __forceinline__ void ldsm_x4(uint32_t& r0, uint32_t& r1,
                                        uint32_t& r2, uint32_t& r3, uint32_t addr) {
    asm volatile("ldmatrix.sync.aligned.m8n8.x4.shared.b16 {%0,%1,%2,%3}, [%4];"
                 : "=r"(r0), "=r"(r1), "=r"(r2), "=r"(r3) : "r"(addr));
}
__device__ __forceinline__ void mma_fp8(float c[4],
                                        uint32_t a0, uint32_t a1, uint32_t a2, uint32_t a3,
                                        uint32_t b0, uint32_t b1) {
    asm volatile(
        "mma.sync.aligned.m16n8k32.row.col.f32.e4m3.e4m3.f32 "
        "{%0,%1,%2,%3}, {%4,%5,%6,%7}, {%8,%9}, {%0,%1,%2,%3};\n"
        : "+f"(c[0]), "+f"(c[1]), "+f"(c[2]), "+f"(c[3])
        : "r"(a0), "r"(a1), "r"(a2), "r"(a3), "r"(b0), "r"(b1));
}

// ---------------------------------------------------------------------------
// Kernel A: projection GEMM (tf32) -> fp8 swizzled q/k arrays.
// q outputs are scaled by 0.125 (exact power of 2 in e4m3).
// ---------------------------------------------------------------------------
__global__ void __launch_bounds__(256) proj_tc(const float* __restrict__ X,
                                               const float* __restrict__ W,
                                               const float* __restrict__ bias,
                                               int which, int bx0)
{
    extern __shared__ uint32_t smemU[];
    uint32_t* As = smemU;               // [128][68]
    uint32_t* Bs = smemU + 128 * 68;    // [64][68]

    const int n0  = (blockIdx.x + bx0) * 64;
    const int m0  = blockIdx.y * 128;
    const int tid = threadIdx.x;
    const int w    = tid >> 5;
    const int lane = tid & 31;

    const int wm = (w & 3) * 32;
    const int wn = (w >> 2) * 32;
    const int qrow = lane >> 2;
    const int qcol = lane & 3;

    float c[2][4][4] = {};

    for (int k0 = 0; k0 < 256; k0 += 64) {
        __syncthreads();
        #pragma unroll
        for (int it = 0; it < 8; ++it) {
            int id = tid + it * 256;
            int r  = id >> 4;
            int q  = id & 15;
            float4 v = *(const float4*)(X + (size_t)(m0 + r) * 256 + k0 + q * 4);
            uint32_t* d = As + r * 68 + q * 4;
            d[0] = f2tf32(v.x); d[1] = f2tf32(v.y); d[2] = f2tf32(v.z); d[3] = f2tf32(v.w);
        }
        #pragma unroll
        for (int it = 0; it < 4; ++it) {
            int id = tid + it * 256;
            int r  = id >> 4;
            int q  = id & 15;
            float4 v = *(const float4*)(W + (size_t)(n0 + r) * 256 + k0 + q * 4);
            uint32_t* d = Bs + r * 68 + q * 4;
            d[0] = f2tf32(v.x); d[1] = f2tf32(v.y); d[2] = f2tf32(v.z); d[3] = f2tf32(v.w);
        }
        __syncthreads();

        const uint32_t* Aw = As + wm * 68;
        const uint32_t* Bw = Bs + wn * 68;
        #pragma unroll
        for (int kk = 0; kk < 8; ++kk) {
            uint32_t a[2][4];
            #pragma unroll
            for (int mt = 0; mt < 2; ++mt) {
                const uint32_t* p = Aw + (mt * 16 + qrow) * 68 + kk * 8 + qcol;
                a[mt][0] = p[0];
                a[mt][1] = p[8 * 68];
                a[mt][2] = p[4];
                a[mt][3] = p[8 * 68 + 4];
            }
            uint32_t b[4][2];
            #pragma unroll
            for (int nt = 0; nt < 4; ++nt) {
                const uint32_t* p = Bw + (nt * 8 + qrow) * 68 + kk * 8 + qcol;
                b[nt][0] = p[0];
                b[nt][1] = p[4];
            }
            #pragma unroll
            for (int mt = 0; mt < 2; ++mt)
                #pragma unroll
                for (int nt = 0; nt < 4; ++nt)
                    mma_tf32(c[mt][nt], a[mt][0], a[mt][1], a[mt][2], a[mt][3],
                             b[nt][0], b[nt][1]);
        }
    }

    const bool isq = (n0 < 256);
    char* arr = which ? (isq ? g_q_vis : g_k_vis) : (isq ? g_q_lang : g_k_lang);
    const float qsc = isq ? 0.125f : 1.0f;   // fold 1/sqrt(hd) into q (exact)

    #pragma unroll
    for (int mt = 0; mt < 2; ++mt) {
        #pragma unroll
        for (int nt = 0; nt < 4; ++nt) {
            const int n  = n0 + wn + nt * 8 + qcol * 2;
            const int cl = n & 255;
            const float b0 = __ldg(bias + n), b1 = __ldg(bias + n + 1);
            const int r0 = m0 + wm + mt * 16 + qrow;
            const int r1 = r0 + 8;
            uint16_t v0 = pack_fp8x2((c[mt][nt][0] + b0) * qsc, (c[mt][nt][1] + b1) * qsc);
            uint16_t v1 = pack_fp8x2((c[mt][nt][2] + b0) * qsc, (c[mt][nt][3] + b1) * qsc);
            uint32_t o0 = (uint32_t)r0 * 256 + ((((cl >> 4) ^ (r0 & 7)) << 4) | (cl & 15));
            uint32_t o1 = (uint32_t)r1 * 256 + ((((cl >> 4) ^ (r1 & 7)) << 4) | (cl & 15));
            *(uint16_t*)(arr + o0) = v0;
            *(uint16_t*)(arr + o1) = v1;
        }
    }
}

// ---------------------------------------------------------------------------
// top3 helper — branchless sorted-triple local insert + shuffle merge.
// ---------------------------------------------------------------------------
template<int NB>
__device__ __forceinline__ float top3_sum(const float* v, int lane) {
    float t1 = -1e30f, t2 = -1e30f, t3 = -1e30f;
    #pragma unroll
    for (int bi = 0; bi < NB; ++bi) {
        float x  = v[bi * 32 + lane];
        float m2 = fminf(t1, x);
        t1 = fmaxf(t1, x);
        t3 = fmaxf(t3, fminf(t2, m2));
        t2 = fmaxf(t2, m2);
    }
    #pragma unroll
    for (int off = 16; off; off >>= 1) {
        float o1 = __shfl_xor_sync(0xffffffffu, t1, off);
        float o2 = __shfl_xor_sync(0xffffffffu, t2, off);
        float o3 = __shfl_xor_sync(0xffffffffu, t3, off);
        float c1 = fmaxf(t1, o1);
        float c2 = fmaxf(fminf(t1, o1), fmaxf(t2, o2));
        float c3 = fmaxf(fmaxf(fminf(t1, o2), fminf(t2, o1)), fmaxf(t3, o3));
        t1 = c1; t2 = c2; t3 = c3;
    }
    return t1 + t2 + t3;
}

// ---------------------------------------------------------------------------
// Kernel B1: v2t fused sim (fp8, pre-scaled q). WR=2, WC=4: M=32, NT=64.
// 256 thr, 3 CTAs/SM. grid (32,16) x NITER=16 = 512 blocks (R15 config).
// ---------------------------------------------------------------------------
__global__ void __launch_bounds__(256, 3)
sim_v2t(const char* __restrict__ anch_q,
        const char* __restrict__ targ_k,
        float* __restrict__ part)
{
    constexpr int WC = 4, M = 32, NT = 64, NITER = 16;
    constexpr int AMS = NT + 4;
    constexpr int OFF_B    = 0;
    constexpr int OFF_A    = OFF_B + NT * 256;
    constexpr int OFF_AM   = OFF_A + M * 256;
    constexpr int OFF_RED  = OFF_AM + M * AMS * 4;
    constexpr int OFF_WACC = OFF_RED + 4 * WC * M * 4;

    extern __shared__ char smem[];
    const uint32_t sbase = (uint32_t)__cvta_generic_to_shared(smem);

    const int j    = blockIdx.x;
    const int z    = blockIdx.y;
    const int tid  = threadIdx.x;
    const int w    = tid >> 5;
    const int lane = tid & 31;

    {
        const char* src = targ_k + (size_t)j * NT * 256;
        #pragma unroll
        for (int id = tid; id < NT * 16; id += 256)
            cpasync16(sbase + OFF_B + id * 16, src + id * 16);
        cpasync_commit();
    }

    const int wm = (w >> 2) * 16;
    const int wn = (w & 3) * 16;
    const int wc = w & 3;
    const int l8  = lane & 7;
    const int sub = lane >> 3;
    const int qrow = lane >> 2;
    const int qcol = lane & 3;

    const uint32_t a_base = sbase + OFF_A + (uint32_t)(wm + l8 + (sub & 1) * 8) * 256;
    const int      a_coff = sub >> 1;
    const uint32_t b_base = sbase + OFF_B + (uint32_t)(wn + l8 + ((sub >> 1) & 1) * 8) * 256;
    const int      b_coff = sub & 1;

    float* redf  = (float*)(smem + OFF_RED);
    float* amf   = (float*)(smem + OFF_AM);
    float* waccf = (float*)(smem + OFF_WACC);

    for (int it = 0; it < NITER; ++it) {
        const int cidx = z * NITER + it;

        __syncthreads();
        {
            const char* src = anch_q + (size_t)cidx * M * 256;
            #pragma unroll
            for (int id = tid; id < M * 16; id += 256)
                cpasync16(sbase + OFF_A + id * 16, src + id * 16);
            cpasync_commit();
            cpasync_wait_all();
        }
        __syncthreads();

        float am[2][4];
        #pragma unroll
        for (int nt = 0; nt < 2; ++nt)
            #pragma unroll
            for (int e = 0; e < 4; ++e) am[nt][e] = 0.f;

        #pragma unroll
        for (int hp = 0; hp < 4; hp += 2) {
            float c[2][2][4];
            #pragma unroll
            for (int hh = 0; hh < 2; ++hh)
                #pragma unroll
                for (int nt = 0; nt < 2; ++nt)
                    #pragma unroll
                    for (int e = 0; e < 4; ++e) c[hh][nt][e] = 0.f;

            #pragma unroll
            for (int hh = 0; hh < 2; ++hh) {
                const int h = hp + hh;
                #pragma unroll
                for (int s = 0; s < 2; ++s) {
                    const int cq = h * 4 + s * 2;
                    uint32_t a0, a1, a2, a3, p0, p1, p2, p3;
                    ldsm_x4(a0, a1, a2, a3, a_base + (((cq + a_coff) ^ l8) << 4));
                    ldsm_x4(p0, p1, p2, p3, b_base + (((cq + b_coff) ^ l8) << 4));
                    mma_fp8(c[hh][0], a0, a1, a2, a3, p0, p1);
                    mma_fp8(c[hh][1], a0, a1, a2, a3, p2, p3);
                }
            }

            #pragma unroll
            for (int hh = 0; hh < 2; ++hh) {
                const int h = hp + hh;
                float z0 = 0.f, z1 = 0.f;
                #pragma unroll
                for (int nt = 0; nt < 2; ++nt) {
                    c[hh][nt][0] = __expf(c[hh][nt][0]);
                    c[hh][nt][1] = __expf(c[hh][nt][1]);
                    c[hh][nt][2] = __expf(c[hh][nt][2]);
                    c[hh][nt][3] = __expf(c[hh][nt][3]);
                    z0 += c[hh][nt][0] + c[hh][nt][1];
                    z1 += c[hh][nt][2] + c[hh][nt][3];
                }
                z0 += __shfl_xor_sync(0xffffffffu, z0, 1);
                z0 += __shfl_xor_sync(0xffffffffu, z0, 2);
                z1 += __shfl_xor_sync(0xffffffffu, z1, 1);
                z1 += __shfl_xor_sync(0xffffffffu, z1, 2);
                if (qcol == 0) {
                    redf[h * WC * M + wc * M + wm + qrow]     = z0;
                    redf[h * WC * M + wc * M + wm + qrow + 8] = z1;
                }
            }
            __syncthreads();

            float rr[2][2];
            #pragma unroll
            for (int hh = 0; hh < 2; ++hh) {
                const int h = hp + hh;
                #pragma unroll
                for (int rp = 0; rp < 2; ++rp) {
                    float zz = 0.f;
                    #pragma unroll
                    for (int x = 0; x < WC; ++x)
                        zz += redf[h * WC * M + x * M + wm + qrow + rp * 8];
                    rr[hh][rp] = 0.25f / zz;
                }
            }

            #pragma unroll
            for (int nt = 0; nt < 2; ++nt) {
                am[nt][0] += c[0][nt][0] * rr[0][0] + c[1][nt][0] * rr[1][0];
                am[nt][1] += c[0][nt][1] * rr[0][0] + c[1][nt][1] * rr[1][0];
                am[nt][2] += c[0][nt][2] * rr[0][1] + c[1][nt][2] * rr[1][1];
                am[nt][3] += c[0][nt][3] * rr[0][1] + c[1][nt][3] * rr[1][1];
            }
        }

        #pragma unroll
        for (int nt = 0; nt < 2; ++nt) {
            const int colb = wn + nt * 8 + qcol * 2;
            *(float2*)&amf[(wm + qrow)     * AMS + colb] = make_float2(am[nt][0], am[nt][1]);
            *(float2*)&amf[(wm + qrow + 8) * AMS + colb] = make_float2(am[nt][2], am[nt][3]);
        }
        __syncthreads();

        float acc = 0.f;
        #pragma unroll
        for (int r2 = 0; r2 < 4; ++r2)
            acc += top3_sum<2>(&amf[(w * 4 + r2) * AMS], lane);
        if (lane == 0) waccf[w] = acc;
        __syncthreads();
        if (tid == 0) {
            float tot = 0.f;
            #pragma unroll
            for (int x = 0; x < 8; ++x) tot += waccf[x];
            const int i = cidx >> 3, slot = cidx & 7;   // 8 chunks per batch
            part[((i * 32 + j) << 3) + slot] = tot;
        }
    }
}

// ---------------------------------------------------------------------------
// Kernel B2: t2v fused sim (fp8, pre-scaled q). 256 thr, M=16, NT=256.
// HPB=4 single pass; 4 barriers/iter; next A-tile prefetched under top-3.
// grid (32,8) x NITER=16 -> 256 blocks = single wave at 2 CTAs/SM.
// Chunks per batch = 4 -> slot decode >>2 / &3.
// ---------------------------------------------------------------------------
__global__ void __launch_bounds__(256, 2)
sim_t2v(const char* __restrict__ anch_q,
        const char* __restrict__ targ_k,
        float* __restrict__ part)
{
    constexpr int NT = 256, M = 16, NITER = 16, AMS = NT + 4;
    constexpr int OFF_B    = 0;
    constexpr int OFF_A    = OFF_B + NT * 256;
    constexpr int OFF_AM   = OFF_A + M * 256;
    constexpr int OFF_RED  = OFF_AM + M * AMS * 4;
    constexpr int OFF_WACC = OFF_RED + 4 * 8 * M * 4;

    extern __shared__ char smem[];
    const uint32_t sbase = (uint32_t)__cvta_generic_to_shared(smem);

    const int j    = blockIdx.x;
    const int z    = blockIdx.y;
    const int tid  = threadIdx.x;
    const int w    = tid >> 5;
    const int lane = tid & 31;

    // ---- B tile + first A tile ----
    {
        const char* src = targ_k + (size_t)j * NT * 256;
        #pragma unroll
        for (int id = tid; id < NT * 16; id += 256)
            cpasync16(sbase + OFF_B + id * 16, src + id * 16);
        const char* srcA = anch_q + (size_t)(z * NITER) * M * 256;
        if (tid < M * 16)
            cpasync16(sbase + OFF_A + tid * 16, srcA + tid * 16);
        cpasync_commit();
        cpasync_wait_all();
    }
    __syncthreads();

    const int wn = w * 32;
    const int l8  = lane & 7;
    const int sub = lane >> 3;
    const int qrow = lane >> 2;
    const int qcol = lane & 3;

    const uint32_t a_base = sbase + OFF_A + (uint32_t)(l8 + (sub & 1) * 8) * 256;
    const int      a_coff = sub >> 1;
    const uint32_t b_base = sbase + OFF_B + (uint32_t)(wn + l8 + ((sub >> 1) & 1) * 8) * 256;
    const int      b_coff = sub & 1;

    float* redf  = (float*)(smem + OFF_RED);
    float* amf   = (float*)(smem + OFF_AM);
    float* waccf = (float*)(smem + OFF_WACC);

    for (int it = 0; it < NITER; ++it) {
        const int cidx = z * NITER + it;

        // ---- MMA all 4 heads ----
        float c[4][4][4];
        #pragma unroll
        for (int h = 0; h < 4; ++h)
            #pragma unroll
            for (int nt = 0; nt < 4; ++nt)
                #pragma unroll
                for (int e = 0; e < 4; ++e) c[h][nt][e] = 0.f;

        #pragma unroll
        for (int h = 0; h < 4; ++h) {
            #pragma unroll
            for (int s = 0; s < 2; ++s) {
                const int cq = h * 4 + s * 2;
                uint32_t a0, a1, a2, a3, p0, p1, p2, p3, q0, q1, q2, q3;
                ldsm_x4(a0, a1, a2, a3, a_base + (((cq + a_coff) ^ l8) << 4));
                ldsm_x4(p0, p1, p2, p3, b_base + (((cq + b_coff) ^ l8) << 4));
                ldsm_x4(q0, q1, q2, q3, b_base + 16 * 256 + (((cq + b_coff) ^ l8) << 4));
                mma_fp8(c[h][0], a0, a1, a2, a3, p0, p1);
                mma_fp8(c[h][1], a0, a1, a2, a3, p2, p3);
                mma_fp8(c[h][2], a0, a1, a2, a3, q0, q1);
                mma_fp8(c[h][3], a0, a1, a2, a3, q2, q3);
            }
        }

        // ---- exp (scale pre-folded into q) + warp-partial Z, all heads ----
        #pragma unroll
        for (int h = 0; h < 4; ++h) {
            float z0 = 0.f, z1 = 0.f;
            #pragma unroll
            for (int nt = 0; nt < 4; ++nt) {
                c[h][nt][0] = __expf(c[h][nt][0]);
                c[h][nt][1] = __expf(c[h][nt][1]);
                c[h][nt][2] = __expf(c[h][nt][2]);
                c[h][nt][3] = __expf(c[h][nt][3]);
                z0 += c[h][nt][0] + c[h][nt][1];
                z1 += c[h][nt][2] + c[h][nt][3];
            }
            z0 += __shfl_xor_sync(0xffffffffu, z0, 1);
            z0 += __shfl_xor_sync(0xffffffffu, z0, 2);
            z1 += __shfl_xor_sync(0xffffffffu, z1, 1);
            z1 += __shfl_xor_sync(0xffffffffu, z1, 2);
            if (qcol == 0) {
                redf[h * 8 * M + w * M + qrow]     = z0;
                redf[h * 8 * M + w * M + qrow + 8] = z1;
            }
        }
        __syncthreads();   // Z ready; A tile now dead -> prefetch next

        if (it + 1 < NITER) {
            const char* src = anch_q + (size_t)(cidx + 1) * M * 256;
            if (tid < M * 16)
                cpasync16(sbase + OFF_A + tid * 16, src + tid * 16);
            cpasync_commit();
        }

        float rr[4][2];
        #pragma unroll
        for (int h = 0; h < 4; ++h)
            #pragma unroll
            for (int rp = 0; rp < 2; ++rp) {
                float zz = 0.f;
                #pragma unroll
                for (int x = 0; x < 8; ++x)
                    zz += redf[h * 8 * M + x * M + qrow + rp * 8];
                rr[h][rp] = 0.25f / zz;
            }

        // ---- am = head-mean, streamed straight into smem stash ----
        #pragma unroll
        for (int nt = 0; nt < 4; ++nt) {
            float a0 = c[0][nt][0]*rr[0][0] + c[1][nt][0]*rr[1][0]
                     + c[2][nt][0]*rr[2][0] + c[3][nt][0]*rr[3][0];
            float a1 = c[0][nt][1]*rr[0][0] + c[1][nt][1]*rr[1][0]
                     + c[2][nt][1]*rr[2][0] + c[3][nt][1]*rr[3][0];
            float a2 = c[0][nt][2]*rr[0][1] + c[1][nt][2]*rr[1][1]
                     + c[2][nt][2]*rr[2][1] + c[3][nt][2]*rr[3][1];
            float a3 = c[0][nt][3]*rr[0][1] + c[1][nt][3]*rr[1][1]
                     + c[2][nt][3]*rr[2][1] + c[3][nt][3]*rr[3][1];
            const int colb = wn + nt * 8 + qcol * 2;
            *(float2*)&amf[qrow       * AMS + colb] = make_float2(a0, a1);
            *(float2*)&amf[(qrow + 8) * AMS + colb] = make_float2(a2, a3);
        }
        __syncthreads();

        // ---- top-3 per anchor row ----
        float acc = 0.f;
        acc += top3_sum<8>(&amf[(w * 2 + 0) * AMS], lane);
        acc += top3_sum<8>(&amf[(w * 2 + 1) * AMS], lane);
        if (lane == 0) waccf[w] = acc;
        __syncthreads();
        if (tid == 0) {
            float tot = 0.f;
            #pragma unroll
            for (int x = 0; x < 8; ++x) tot += waccf[x];
            const int i = cidx >> 2, slot = cidx & 3;   // 4 chunks per batch
            part[((i * 32 + j) << 3) + slot] = tot;
        }
        cpasync_wait_all();
        __syncthreads();   // A(it+1) ready; amf/waccf consumed
    }
}

// ---------------------------------------------------------------------------
// Kernel C: contrastive loss (8 slots per pair; unused slots stay zero)
// ---------------------------------------------------------------------------
__global__ void loss_kernel(const float* __restrict__ part, float* __restrict__ out)
{
    __shared__ float red[64];
    const int t   = threadIdx.x;
    const int dir = t >> 5;
    const int row = t & 31;
    const float* P = part + dir * 8192;
    const float scale = dir ? (100.f / (3.f * 64.f)) : (100.f / (3.f * 256.f));

    float pos = 0.f;
    float t1 = -1e30f, t2 = -1e30f, t3 = -1e30f;
    for (int j = 0; j < 32; ++j) {
        const float* q = &P[(row * 32 + j) << 3];
        float4 a = *(const float4*)q;
        float4 b = *(const float4*)(q + 4);
        float v = (a.x + a.y + a.z + a.w + b.x + b.y + b.z + b.w) * scale;
        if (j == row) { pos = v; continue; }
        if      (v > t1) { t3 = t2; t2 = t1; t1 = v; }
        else if (v > t2) { t3 = t2; t2 = v; }
        else if (v > t3) { t3 = v; }
    }
    const float invT = 1.0f / 0.07f;
    float l0 = pos * invT, l1 = t1 * invT, l2 = t2 * invT, l3 = t3 * invT;
    float m  = fmaxf(fmaxf(l0, l1), fmaxf(l2, l3));
    float Z  = expf(l0 - m) + expf(l1 - m) + expf(l2 - m) + expf(l3 - m);
    red[t] = -(l0 - m - logf(Z));
    __syncthreads();
    if (t == 0) {
        float s0 = 0.f, s1 = 0.f;
        for (int r = 0; r < 32; ++r) { s0 += red[r]; s1 += red[32 + r]; }
        out[0] = 0.5f * (s0 / 32.f) + 0.5f * (s1 / 32.f);
    }
}

// ---------------------------------------------------------------------------
// Launch: critical-path shaping (t2v needs {q_lang, k_vis} -> start early)
// ---------------------------------------------------------------------------
extern "C" void kernel_launch(void* const* d_in, const int* in_sizes, int n_in,
                              void* d_out, int out_size)
{
    const float* lang = (const float*)d_in[0];
    const float* vis  = (const float*)d_in[1];
    const float* W    = (const float*)d_in[2];
    const float* bias = (const float*)d_in[3];

    const int SM_PROJ = (128 * 68 + 64 * 68) * 4;   // 52,224
    const int SM_V2T  = 64*256 + 32*256 + 32*68*4 + 4*4*32*4 + 32;    // 35,360
    const int SM_T2V  = 256*256 + 16*256 + 16*260*4 + 4*8*16*4 + 32;  // 88,352

    static char *p_ql = nullptr, *p_kl = nullptr, *p_qv = nullptr, *p_kv = nullptr;
    static float *p_part = nullptr;
    static cudaStream_t s2;
    static cudaEvent_t evF, evLang, evT;
    if (!p_ql) {
        cudaGetSymbolAddress((void**)&p_ql, g_q_lang);
        cudaGetSymbolAddress((void**)&p_kl, g_k_lang);
        cudaGetSymbolAddress((void**)&p_qv, g_q_vis);
        cudaGetSymbolAddress((void**)&p_kv, g_k_vis);
        cudaGetSymbolAddress((void**)&p_part, g_part);
        cudaFuncSetAttribute((const void*)proj_tc,
                             cudaFuncAttributeMaxDynamicSharedMemorySize, SM_PROJ);
        cudaFuncSetAttribute((const void*)sim_v2t,
                             cudaFuncAttributeMaxDynamicSharedMemorySize, SM_V2T);
        cudaFuncSetAttribute((const void*)sim_t2v,
                             cudaFuncAttributeMaxDynamicSharedMemorySize, SM_T2V);
        cudaStreamCreateWithFlags(&s2, cudaStreamNonBlocking);
        cudaEventCreateWithFlags(&evF,    cudaEventDisableTiming);
        cudaEventCreateWithFlags(&evLang, cudaEventDisableTiming);
        cudaEventCreateWithFlags(&evT,    cudaEventDisableTiming);
    }

    // fork s2 into the captured graph
    cudaEventRecord(evF, 0);
    cudaStreamWaitEvent(s2, evF, 0);

    // s2: k-half of vis projection, then t2v (the long pole) ASAP
    proj_tc<<<dim3(4, 64), 256, SM_PROJ, s2>>>(vis, W, bias, 1, 4);   // k_vis

    // s0: lang projection (q_lang + k_lang), then q-half of vis
    proj_tc<<<dim3(8, 16), 256, SM_PROJ, 0>>>(lang, W, bias, 0, 0);   // q/k_lang
    cudaEventRecord(evLang, 0);
    proj_tc<<<dim3(4, 64), 256, SM_PROJ, 0>>>(vis, W, bias, 1, 0);    // q_vis

    // t2v: waits k_vis (s2 order) + q_lang (evLang)
    cudaStreamWaitEvent(s2, evLang, 0);
    sim_t2v<<<dim3(32, 8), 256, SM_T2V, s2>>>(p_ql, p_kv, p_part + 8192);

    // v2t: deps (k_lang, q_vis) are both earlier in s0
    sim_v2t<<<dim3(32, 16), 256, SM_V2T, 0>>>(p_qv, p_kl, p_part);

    // join before loss
    cudaEventRecord(evT, s2);
    cudaStreamWaitEvent(0, evT, 0);

    loss_kernel<<<1, 64, 0, 0>>>(p_part, (float*)d_out);
}